// round 2
// baseline (speedup 1.0000x reference)
#include <cuda_runtime.h>

// exp(-d2 / (2*0.3^2)) = exp2(-K * d2), K = log2(e) / 0.18
#define KCONST 8.014972449383130f
#define BLOCK 256
#define PTS 3

__global__ __launch_bounds__(BLOCK, 1)
void rbf_kernel(const float* __restrict__ x, const float* __restrict__ cen,
                const float* __restrict__ cu, const float* __restrict__ cv,
                const float* __restrict__ cw, float* __restrict__ out,
                int n, int m, int mp, int tot)
{
    extern __shared__ float4 sm[];
    float4* sc = sm;        // [mp] : {cx, cy, cz, -K*|c|^2}
    float4* sq = sm + mp;   // [mp] : {coeff_u, coeff_v, coeff_w, 0}

    for (int j = threadIdx.x; j < mp; j += BLOCK) {
        if (j < m) {
            float c0 = cen[3*j], c1 = cen[3*j+1], c2 = cen[3*j+2];
            sc[j] = make_float4(c0, c1, c2,
                                -KCONST * (c0*c0 + c1*c1 + c2*c2));
            sq[j] = make_float4(cu[j], cv[j], cw[j], 0.f);
        } else {
            // pad: exponent -> -1e30 => ex2 -> 0, coeffs 0 => no contribution
            sc[j] = make_float4(0.f, 0.f, 0.f, -1e30f);
            sq[j] = make_float4(0.f, 0.f, 0.f, 0.f);
        }
    }
    __syncthreads();

    int g = blockIdx.x * BLOCK + threadIdx.x;

    float a0[PTS], a1[PTS], a2[PTS], bb[PTS];
    float px[PTS], py[PTS], pz[PTS], xs[PTS];
#pragma unroll
    for (int s = 0; s < PTS; s++) {
        int i = g + s * tot;
        int ic = (i < n) ? i : 0;   // clamp loads; stores guarded below
        float x0 = x[3*ic], x1 = x[3*ic+1], x2 = x[3*ic+2];
        px[s] = x0; py[s] = x1; pz[s] = x2;
        float xsq = x0*x0 + x1*x1 + x2*x2;
        xs[s] = xsq;
        a0[s] = 2.f * KCONST * x0;
        a1[s] = 2.f * KCONST * x1;
        a2[s] = 2.f * KCONST * x2;
        bb[s] = -KCONST * xsq;
    }

    float su[PTS], sv[PTS], sw[PTS];
#pragma unroll
    for (int s = 0; s < PTS; s++) { su[s] = 0.f; sv[s] = 0.f; sw[s] = 0.f; }

#pragma unroll 4
    for (int j = 0; j < mp; j++) {
        float4 c = sc[j];   // broadcast across warp -> conflict-free
        float4 q = sq[j];
#pragma unroll
        for (int s = 0; s < PTS; s++) {
            // t = -K * dist2 = 2K*x.c - K*|x|^2 - K*|c|^2   (always <= ~0)
            float t = fmaf(a0[s], c.x,
                      fmaf(a1[s], c.y,
                      fmaf(a2[s], c.z, c.w + bb[s])));
            float e;
            asm("ex2.approx.ftz.f32 %0, %1;" : "=f"(e) : "f"(t));
            su[s] = fmaf(e, q.x, su[s]);
            sv[s] = fmaf(e, q.y, sv[s]);
            sw[s] = fmaf(e, q.z, sw[s]);
        }
    }

#pragma unroll
    for (int s = 0; s < PTS; s++) {
        int i = g + s * tot;
        if (i < n) {
            float r  = sqrtf(xs[s]);
            float om = 1.f - r;                     // base = x * (1 - ||x||)
            out[3*i]   = fmaf(px[s], om, su[s]);
            out[3*i+1] = fmaf(py[s], om, sv[s]);
            out[3*i+2] = fmaf(pz[s], om, sw[s]);
        }
    }
}

extern "C" void kernel_launch(void* const* d_in, const int* in_sizes, int n_in,
                              void* d_out, int out_size)
{
    const float* x   = (const float*)d_in[0];
    const float* cen = (const float*)d_in[1];
    const float* cu  = (const float*)d_in[2];
    const float* cv  = (const float*)d_in[3];
    const float* cw  = (const float*)d_in[4];
    float* out = (float*)d_out;

    int n = in_sizes[0] / 3;   // 100000
    int m = in_sizes[2];       // 3375
    int mp = (m + 3) & ~3;     // pad to multiple of 4 for clean unroll

    size_t smem = (size_t)2 * mp * sizeof(float4);  // ~108 KB
    cudaFuncSetAttribute(rbf_kernel,
                         cudaFuncAttributeMaxDynamicSharedMemorySize,
                         (int)smem);

    int grid = (n + BLOCK * PTS - 1) / (BLOCK * PTS);
    int tot  = grid * BLOCK;
    rbf_kernel<<<grid, BLOCK, smem>>>(x, cen, cu, cv, cw, out, n, m, mp, tot);
}

// round 3
// speedup vs baseline: 1.3095x; 1.3095x over previous
#include <cuda_runtime.h>

// exp(-d2 / (2*0.3^2)) = exp2(-K * d2), K = log2(e) / 0.18
#define KCONST 8.014972449383130f
#define BLOCK 384

typedef unsigned long long u64;

__device__ __forceinline__ u64 fma2(u64 a, u64 b, u64 c) {
    u64 d;
    asm("fma.rn.f32x2 %0, %1, %2, %3;" : "=l"(d) : "l"(a), "l"(b), "l"(c));
    return d;
}
__device__ __forceinline__ u64 add2(u64 a, u64 b) {
    u64 d;
    asm("add.rn.f32x2 %0, %1, %2;" : "=l"(d) : "l"(a), "l"(b));
    return d;
}
__device__ __forceinline__ u64 pack2(float lo, float hi) {
    u64 d;
    asm("mov.b64 %0, {%1, %2};" : "=l"(d) : "f"(lo), "f"(hi));
    return d;
}
__device__ __forceinline__ void unpack2(u64 v, float& lo, float& hi) {
    asm("mov.b64 {%0, %1}, %2;" : "=f"(lo), "=f"(hi) : "l"(v));
}
__device__ __forceinline__ float ex2f(float t) {
    float e;
    asm("ex2.approx.ftz.f32 %0, %1;" : "=f"(e) : "f"(t));
    return e;
}

// smem layout per center j (pre-duplicated for f32x2 operands):
//   scA[j] = {cx,cx, cy,cy}        (float4, read as ulonglong2)
//   scB[j] = {cz,cz, cw,cw}        cw = -K*|c|^2
//   sqA[j] = {u,u,  v,v}
//   sqB[j] = {w,w}                 (float2, read as u64)
__global__ __launch_bounds__(BLOCK, 1)
void rbf_kernel(const float* __restrict__ x, const float* __restrict__ cen,
                const float* __restrict__ cu, const float* __restrict__ cv,
                const float* __restrict__ cw, float* __restrict__ out,
                int n, int m, int mp, int tot)
{
    extern __shared__ float4 sm[];
    float4* scA = sm;
    float4* scB = sm + mp;
    float4* sqA = sm + 2 * mp;
    float2* sqB = (float2*)(sm + 3 * mp);

    for (int j = threadIdx.x; j < mp; j += BLOCK) {
        if (j < m) {
            float c0 = cen[3*j], c1 = cen[3*j+1], c2 = cen[3*j+2];
            float cs = -KCONST * (c0*c0 + c1*c1 + c2*c2);
            scA[j] = make_float4(c0, c0, c1, c1);
            scB[j] = make_float4(c2, c2, cs, cs);
            float u = cu[j], v = cv[j], w = cw[j];
            sqA[j] = make_float4(u, u, v, v);
            sqB[j] = make_float2(w, w);
        } else {
            // pad: exponent -> -1e30 => ex2 -> 0; coeffs 0 => no contribution
            scA[j] = make_float4(0.f, 0.f, 0.f, 0.f);
            scB[j] = make_float4(0.f, 0.f, -1e30f, -1e30f);
            sqA[j] = make_float4(0.f, 0.f, 0.f, 0.f);
            sqB[j] = make_float2(0.f, 0.f);
        }
    }
    __syncthreads();

    int g = blockIdx.x * BLOCK + threadIdx.x;

    // two points per thread: i0 = g, i1 = g + tot (strided; clamped loads)
    float px[2], py[2], pz[2], xs[2];
    float a0s[2], a1s[2], a2s[2], bbs[2];
#pragma unroll
    for (int s = 0; s < 2; s++) {
        int i = g + s * tot;
        int ic = (i < n) ? i : 0;
        float x0 = x[3*ic], x1 = x[3*ic+1], x2 = x[3*ic+2];
        px[s] = x0; py[s] = x1; pz[s] = x2;
        float xsq = x0*x0 + x1*x1 + x2*x2;
        xs[s] = xsq;
        a0s[s] = 2.f * KCONST * x0;
        a1s[s] = 2.f * KCONST * x1;
        a2s[s] = 2.f * KCONST * x2;
        bbs[s] = -KCONST * xsq;
    }

    u64 a0p = pack2(a0s[0], a0s[1]);
    u64 a1p = pack2(a1s[0], a1s[1]);
    u64 a2p = pack2(a2s[0], a2s[1]);
    u64 bbp = pack2(bbs[0], bbs[1]);

    u64 su = 0, sv = 0, sw = 0;   // packed {0.f, 0.f}

    const ulonglong2* pA = (const ulonglong2*)scA;
    const ulonglong2* pB = (const ulonglong2*)scB;
    const ulonglong2* pQ = (const ulonglong2*)sqA;
    const u64*        pW = (const u64*)sqB;

#pragma unroll 4
    for (int j = 0; j < mp; j++) {
        ulonglong2 cxy = pA[j];   // .x = {cx,cx}, .y = {cy,cy}
        ulonglong2 czw = pB[j];   // .x = {cz,cz}, .y = {cs,cs}
        ulonglong2 quv = pQ[j];   // .x = {u,u},   .y = {v,v}
        u64        qw  = pW[j];   // {w,w}

        // t = 2K*x.c - K|x|^2 - K|c|^2  (packed over 2 points)
        u64 t = add2(czw.y, bbp);
        t = fma2(a2p, czw.x, t);
        t = fma2(a1p, cxy.y, t);
        t = fma2(a0p, cxy.x, t);

        float t0, t1;
        unpack2(t, t0, t1);
        float e0 = ex2f(t0);
        float e1 = ex2f(t1);
        u64 e = pack2(e0, e1);

        su = fma2(e, quv.x, su);
        sv = fma2(e, quv.y, sv);
        sw = fma2(e, qw,    sw);
    }

    float su0, su1, sv0, sv1, sw0, sw1;
    unpack2(su, su0, su1);
    unpack2(sv, sv0, sv1);
    unpack2(sw, sw0, sw1);
    float suu[2] = {su0, su1}, svv[2] = {sv0, sv1}, sww[2] = {sw0, sw1};

#pragma unroll
    for (int s = 0; s < 2; s++) {
        int i = g + s * tot;
        if (i < n) {
            float r  = sqrtf(xs[s]);
            float om = 1.f - r;                 // base = x * (1 - ||x||)
            out[3*i]   = fmaf(px[s], om, suu[s]);
            out[3*i+1] = fmaf(py[s], om, svv[s]);
            out[3*i+2] = fmaf(pz[s], om, sww[s]);
        }
    }
}

extern "C" void kernel_launch(void* const* d_in, const int* in_sizes, int n_in,
                              void* d_out, int out_size)
{
    const float* x   = (const float*)d_in[0];
    const float* cen = (const float*)d_in[1];
    const float* cu  = (const float*)d_in[2];
    const float* cv  = (const float*)d_in[3];
    const float* cw  = (const float*)d_in[4];
    float* out = (float*)d_out;

    int n = in_sizes[0] / 3;   // 100000
    int m = in_sizes[2];       // 3375
    int mp = (m + 3) & ~3;     // 3376

    // 3 * float4 + 1 * float2 per center = 56 B  -> ~189 KB
    size_t smem = (size_t)mp * (3 * sizeof(float4) + sizeof(float2));
    cudaFuncSetAttribute(rbf_kernel,
                         cudaFuncAttributeMaxDynamicSharedMemorySize,
                         (int)smem);

    int grid = (n + BLOCK * 2 - 1) / (BLOCK * 2);   // 131 -> single wave
    int tot  = grid * BLOCK;
    rbf_kernel<<<grid, BLOCK, smem>>>(x, cen, cu, cv, cw, out, n, m, mp, tot);
}

// round 4
// speedup vs baseline: 1.4529x; 1.1096x over previous
#include <cuda_runtime.h>

// exp(-d2 / (2*0.3^2)) = exp2(-K * d2), K = log2(e) / 0.18
#define KCONST 8.014972449383130f
#define BLOCK 256
#define PTS 3

typedef unsigned long long u64;

__device__ __forceinline__ u64 fma2(u64 a, u64 b, u64 c) {
    u64 d;
    asm("fma.rn.f32x2 %0, %1, %2, %3;" : "=l"(d) : "l"(a), "l"(b), "l"(c));
    return d;
}
__device__ __forceinline__ u64 add2(u64 a, u64 b) {
    u64 d;
    asm("add.rn.f32x2 %0, %1, %2;" : "=l"(d) : "l"(a), "l"(b));
    return d;
}
__device__ __forceinline__ u64 pack2(float lo, float hi) {
    u64 d;
    asm("mov.b64 %0, {%1, %2};" : "=l"(d) : "f"(lo), "f"(hi));
    return d;
}
__device__ __forceinline__ void unpack2(u64 v, float& lo, float& hi) {
    asm("mov.b64 {%0, %1}, %2;" : "=f"(lo), "=f"(hi) : "l"(v));
}
__device__ __forceinline__ float ex2f(float t) {
    float e;
    asm("ex2.approx.ftz.f32 %0, %1;" : "=f"(e) : "f"(t));
    return e;
}

// Packed-lane = 2 adjacent CENTERS (no duplication in smem).
// Per center-pair p (centers 2p, 2p+1):
//   sA[p] = {c0x,c1x, c0y,c1y}
//   sB[p] = {c0z,c1z, cs0,cs1}    cs = -K*|c|^2
//   sQ[p] = {u0,u1,  v0,v1}
//   sW[p] = {w0,w1}
__global__ __launch_bounds__(BLOCK, 1)
void rbf_kernel(const float* __restrict__ x, const float* __restrict__ cen,
                const float* __restrict__ cu, const float* __restrict__ cv,
                const float* __restrict__ cw, float* __restrict__ out,
                int n, int m, int P, int tot)
{
    extern __shared__ float4 sm[];
    float4* sA = sm;
    float4* sB = sm + P;
    float4* sQ = sm + 2 * P;
    float2* sW = (float2*)(sm + 3 * P);

    for (int p = threadIdx.x; p < P; p += BLOCK) {
        float c[2][3], cs[2], qu[2], qv[2], qw[2];
#pragma unroll
        for (int h = 0; h < 2; h++) {
            int e = 2 * p + h;
            if (e < m) {
                c[h][0] = cen[3*e]; c[h][1] = cen[3*e+1]; c[h][2] = cen[3*e+2];
                cs[h] = -KCONST * (c[h][0]*c[h][0] + c[h][1]*c[h][1] + c[h][2]*c[h][2]);
                qu[h] = cu[e]; qv[h] = cv[e]; qw[h] = cw[e];
            } else {
                // pad: exponent -> -1e30 => ex2 -> 0; coeffs 0 => no contribution
                c[h][0] = c[h][1] = c[h][2] = 0.f;
                cs[h] = -1e30f;
                qu[h] = qv[h] = qw[h] = 0.f;
            }
        }
        sA[p] = make_float4(c[0][0], c[1][0], c[0][1], c[1][1]);
        sB[p] = make_float4(c[0][2], c[1][2], cs[0], cs[1]);
        sQ[p] = make_float4(qu[0], qu[1], qv[0], qv[1]);
        sW[p] = make_float2(qw[0], qw[1]);
    }
    __syncthreads();

    int g = blockIdx.x * BLOCK + threadIdx.x;

    // PTS points per thread (strided by tot); per-point scalars duplicated
    // ONCE into packed registers here.
    float px[PTS], py[PTS], pz[PTS], xs[PTS];
    u64 a0p[PTS], a1p[PTS], a2p[PTS], bbp[PTS];
#pragma unroll
    for (int s = 0; s < PTS; s++) {
        int i = g + s * tot;
        int ic = (i < n) ? i : 0;     // clamp loads; stores guarded below
        float x0 = x[3*ic], x1 = x[3*ic+1], x2 = x[3*ic+2];
        px[s] = x0; py[s] = x1; pz[s] = x2;
        float xsq = x0*x0 + x1*x1 + x2*x2;
        xs[s] = xsq;
        float a0 = 2.f * KCONST * x0;
        float a1 = 2.f * KCONST * x1;
        float a2 = 2.f * KCONST * x2;
        float bb = -KCONST * xsq;
        a0p[s] = pack2(a0, a0);
        a1p[s] = pack2(a1, a1);
        a2p[s] = pack2(a2, a2);
        bbp[s] = pack2(bb, bb);
    }

    u64 su[PTS], sv[PTS], sw[PTS];   // packed over the 2 center lanes
#pragma unroll
    for (int s = 0; s < PTS; s++) { su[s] = 0; sv[s] = 0; sw[s] = 0; }

    const ulonglong2* pA = (const ulonglong2*)sA;
    const ulonglong2* pB = (const ulonglong2*)sB;
    const ulonglong2* pQ = (const ulonglong2*)sQ;
    const u64*        pW = (const u64*)sW;

#pragma unroll 2
    for (int p = 0; p < P; p++) {
        ulonglong2 cxy = pA[p];   // .x = {c0x,c1x}, .y = {c0y,c1y}
        ulonglong2 czs = pB[p];   // .x = {c0z,c1z}, .y = {cs0,cs1}
        ulonglong2 quv = pQ[p];   // .x = {u0,u1},   .y = {v0,v1}
        u64        qw  = pW[p];   // {w0,w1}

#pragma unroll
        for (int s = 0; s < PTS; s++) {
            // t = 2K*x.c - K|x|^2 - K|c|^2   (packed over 2 centers)
            u64 t = add2(czs.y, bbp[s]);
            t = fma2(a2p[s], czs.x, t);
            t = fma2(a1p[s], cxy.y, t);
            t = fma2(a0p[s], cxy.x, t);

            float t0, t1;
            unpack2(t, t0, t1);
            float e0 = ex2f(t0);
            float e1 = ex2f(t1);
            u64 e = pack2(e0, e1);

            su[s] = fma2(e, quv.x, su[s]);
            sv[s] = fma2(e, quv.y, sv[s]);
            sw[s] = fma2(e, qw,    sw[s]);
        }
    }

#pragma unroll
    for (int s = 0; s < PTS; s++) {
        int i = g + s * tot;
        if (i < n) {
            float u0, u1, v0, v1, w0, w1;
            unpack2(su[s], u0, u1);
            unpack2(sv[s], v0, v1);
            unpack2(sw[s], w0, w1);
            float r  = sqrtf(xs[s]);
            float om = 1.f - r;                 // base = x * (1 - ||x||)
            out[3*i]   = fmaf(px[s], om, u0 + u1);
            out[3*i+1] = fmaf(py[s], om, v0 + v1);
            out[3*i+2] = fmaf(pz[s], om, w0 + w1);
        }
    }
}

extern "C" void kernel_launch(void* const* d_in, const int* in_sizes, int n_in,
                              void* d_out, int out_size)
{
    const float* x   = (const float*)d_in[0];
    const float* cen = (const float*)d_in[1];
    const float* cu  = (const float*)d_in[2];
    const float* cv  = (const float*)d_in[3];
    const float* cw  = (const float*)d_in[4];
    float* out = (float*)d_out;

    int n = in_sizes[0] / 3;     // 100000
    int m = in_sizes[2];         // 3375
    int P = (m + 1) / 2;         // 1688 center pairs (pad to even)

    // 3 * float4 + 1 * float2 per pair = 56 B -> ~94.5 KB
    size_t smem = (size_t)P * (3 * sizeof(float4) + sizeof(float2));
    cudaFuncSetAttribute(rbf_kernel,
                         cudaFuncAttributeMaxDynamicSharedMemorySize,
                         (int)smem);

    int grid = (n + BLOCK * PTS - 1) / (BLOCK * PTS);   // 131 -> single wave
    int tot  = grid * BLOCK;
    rbf_kernel<<<grid, BLOCK, smem>>>(x, cen, cu, cv, cw, out, n, m, P, tot);
}

// round 5
// speedup vs baseline: 1.5424x; 1.0616x over previous
#include <cuda_runtime.h>

// exp(-d2 / (2*0.3^2)) = exp2(-K * d2), K = log2(e) / 0.18
#define KCONST 8.014972449383130f
#define BLOCK 384
#define PTS 2

typedef unsigned long long u64;

__device__ __forceinline__ u64 fma2(u64 a, u64 b, u64 c) {
    u64 d;
    asm("fma.rn.f32x2 %0, %1, %2, %3;" : "=l"(d) : "l"(a), "l"(b), "l"(c));
    return d;
}
__device__ __forceinline__ u64 mul2(u64 a, u64 b) {
    u64 d;
    asm("mul.rn.f32x2 %0, %1, %2;" : "=l"(d) : "l"(a), "l"(b));
    return d;
}
__device__ __forceinline__ u64 add2(u64 a, u64 b) {
    u64 d;
    asm("add.rn.f32x2 %0, %1, %2;" : "=l"(d) : "l"(a), "l"(b));
    return d;
}
__device__ __forceinline__ u64 pack2(float lo, float hi) {
    u64 d;
    asm("mov.b64 %0, {%1, %2};" : "=l"(d) : "f"(lo), "f"(hi));
    return d;
}
__device__ __forceinline__ void unpack2(u64 v, float& lo, float& hi) {
    asm("mov.b64 {%0, %1}, %2;" : "=f"(lo), "=f"(hi) : "l"(v));
}
// both-lane ex2 in one asm scope: lets ptxas alias e0/e1 onto the
// halves of the input/output register pairs (no real MOVs).
__device__ __forceinline__ u64 ex2_pair(u64 t) {
    u64 e;
    asm("{\n\t"
        ".reg .f32 e0, e1;\n\t"
        "mov.b64 {e0, e1}, %1;\n\t"
        "ex2.approx.ftz.f32 e0, e0;\n\t"
        "ex2.approx.ftz.f32 e1, e1;\n\t"
        "mov.b64 %0, {e0, e1};\n\t"
        "}" : "=l"(e) : "l"(t));
    return e;
}

// Packed-lane = 2 adjacent CENTERS (no duplication in smem).
// Per center-pair p (centers 2p, 2p+1):
//   sA[p] = {c0x,c1x, c0y,c1y}
//   sB[p] = {c0z,c1z, cs0,cs1}    cs = -K*|c|^2
//   sQ[p] = {u0,u1,  v0,v1}
//   sW[p] = {w0,w1}
__global__ __launch_bounds__(BLOCK, 1)
void rbf_kernel(const float* __restrict__ x, const float* __restrict__ cen,
                const float* __restrict__ cu, const float* __restrict__ cv,
                const float* __restrict__ cw, float* __restrict__ out,
                int n, int m, int P, int tot)
{
    extern __shared__ float4 sm[];
    float4* sA = sm;
    float4* sB = sm + P;
    float4* sQ = sm + 2 * P;
    float2* sW = (float2*)(sm + 3 * P);

    for (int p = threadIdx.x; p < P; p += BLOCK) {
        float c[2][3], cs[2], qu[2], qv[2], qw[2];
#pragma unroll
        for (int h = 0; h < 2; h++) {
            int e = 2 * p + h;
            if (e < m) {
                c[h][0] = cen[3*e]; c[h][1] = cen[3*e+1]; c[h][2] = cen[3*e+2];
                cs[h] = -KCONST * (c[h][0]*c[h][0] + c[h][1]*c[h][1] + c[h][2]*c[h][2]);
                qu[h] = cu[e]; qv[h] = cv[e]; qw[h] = cw[e];
            } else {
                // pad: exponent -> -1e30 => ex2 -> 0; coeffs 0 => no contribution
                c[h][0] = c[h][1] = c[h][2] = 0.f;
                cs[h] = -1e30f;
                qu[h] = qv[h] = qw[h] = 0.f;
            }
        }
        sA[p] = make_float4(c[0][0], c[1][0], c[0][1], c[1][1]);
        sB[p] = make_float4(c[0][2], c[1][2], cs[0], cs[1]);
        sQ[p] = make_float4(qu[0], qu[1], qv[0], qv[1]);
        sW[p] = make_float2(qw[0], qw[1]);
    }
    __syncthreads();

    int g = blockIdx.x * BLOCK + threadIdx.x;

    // PTS points per thread (strided by tot); per-point scalars duplicated
    // ONCE into packed registers here.
    float px[PTS], py[PTS], pz[PTS], xs[PTS];
    u64 a0p[PTS], a1p[PTS], a2p[PTS], bbp[PTS];
#pragma unroll
    for (int s = 0; s < PTS; s++) {
        int i = g + s * tot;
        int ic = (i < n) ? i : 0;     // clamp loads; stores guarded below
        float x0 = x[3*ic], x1 = x[3*ic+1], x2 = x[3*ic+2];
        px[s] = x0; py[s] = x1; pz[s] = x2;
        float xsq = x0*x0 + x1*x1 + x2*x2;
        xs[s] = xsq;
        float a0 = 2.f * KCONST * x0;
        float a1 = 2.f * KCONST * x1;
        float a2 = 2.f * KCONST * x2;
        float bb = -KCONST * xsq;
        a0p[s] = pack2(a0, a0);
        a1p[s] = pack2(a1, a1);
        a2p[s] = pack2(a2, a2);
        bbp[s] = pack2(bb, bb);
    }

    u64 su[PTS], sv[PTS], sw[PTS];   // packed over the 2 center lanes
#pragma unroll
    for (int s = 0; s < PTS; s++) { su[s] = 0; sv[s] = 0; sw[s] = 0; }

    const ulonglong2* pA = (const ulonglong2*)sA;
    const ulonglong2* pB = (const ulonglong2*)sB;
    const ulonglong2* pQ = (const ulonglong2*)sQ;
    const u64*        pW = (const u64*)sW;

#pragma unroll 2
    for (int p = 0; p < P; p++) {
        ulonglong2 cxy = pA[p];   // .x = {c0x,c1x}, .y = {c0y,c1y}
        ulonglong2 czs = pB[p];   // .x = {c0z,c1z}, .y = {cs0,cs1}
        ulonglong2 quv = pQ[p];   // .x = {u0,u1},   .y = {v0,v1}
        u64        qw  = pW[p];   // {w0,w1}

#pragma unroll
        for (int s = 0; s < PTS; s++) {
            // t = 2K*x.c - K|x|^2 - K|c|^2  (packed over 2 centers)
            // depth-3 tree instead of 4-deep serial chain:
            u64 tA = mul2(a0p[s], cxy.x);
            tA = fma2(a1p[s], cxy.y, tA);
            u64 tB = add2(czs.y, bbp[s]);
            tB = fma2(a2p[s], czs.x, tB);
            u64 t = add2(tA, tB);

            u64 e = ex2_pair(t);

            su[s] = fma2(e, quv.x, su[s]);
            sv[s] = fma2(e, quv.y, sv[s]);
            sw[s] = fma2(e, qw,    sw[s]);
        }
    }

#pragma unroll
    for (int s = 0; s < PTS; s++) {
        int i = g + s * tot;
        if (i < n) {
            float u0, u1, v0, v1, w0, w1;
            unpack2(su[s], u0, u1);
            unpack2(sv[s], v0, v1);
            unpack2(sw[s], w0, w1);
            float r  = sqrtf(xs[s]);
            float om = 1.f - r;                 // base = x * (1 - ||x||)
            out[3*i]   = fmaf(px[s], om, u0 + u1);
            out[3*i+1] = fmaf(py[s], om, v0 + v1);
            out[3*i+2] = fmaf(pz[s], om, w0 + w1);
        }
    }
}

extern "C" void kernel_launch(void* const* d_in, const int* in_sizes, int n_in,
                              void* d_out, int out_size)
{
    const float* x   = (const float*)d_in[0];
    const float* cen = (const float*)d_in[1];
    const float* cu  = (const float*)d_in[2];
    const float* cv  = (const float*)d_in[3];
    const float* cw  = (const float*)d_in[4];
    float* out = (float*)d_out;

    int n = in_sizes[0] / 3;     // 100000
    int m = in_sizes[2];         // 3375
    int P = (m + 1) / 2;         // 1688 center pairs (pad to even)

    // 3 * float4 + 1 * float2 per pair = 56 B -> ~94.5 KB
    size_t smem = (size_t)P * (3 * sizeof(float4) + sizeof(float2));
    cudaFuncSetAttribute(rbf_kernel,
                         cudaFuncAttributeMaxDynamicSharedMemorySize,
                         (int)smem);

    int grid = (n + BLOCK * PTS - 1) / (BLOCK * PTS);   // 131 -> single wave
    int tot  = grid * BLOCK;
    rbf_kernel<<<grid, BLOCK, smem>>>(x, cen, cu, cv, cw, out, n, m, P, tot);
}

// round 6
// speedup vs baseline: 1.6542x; 1.0725x over previous
#include <cuda_runtime.h>

// exp(-d2 / (2*0.3^2)) = exp2(-K * d2), K = log2(e) / 0.18
#define KCONST 8.014972449383130f
#define BLOCK 384
#define PTS 2
#define NPMAX 131072   // >= n (n = 100000 for this problem)

typedef unsigned long long u64;

// partial RBF sums: [half][point][3]
__device__ float g_partial[2 * NPMAX * 3];

__device__ __forceinline__ u64 fma2(u64 a, u64 b, u64 c) {
    u64 d;
    asm("fma.rn.f32x2 %0, %1, %2, %3;" : "=l"(d) : "l"(a), "l"(b), "l"(c));
    return d;
}
__device__ __forceinline__ u64 add2(u64 a, u64 b) {
    u64 d;
    asm("add.rn.f32x2 %0, %1, %2;" : "=l"(d) : "l"(a), "l"(b));
    return d;
}
__device__ __forceinline__ u64 pack2(float lo, float hi) {
    u64 d;
    asm("mov.b64 %0, {%1, %2};" : "=l"(d) : "f"(lo), "f"(hi));
    return d;
}
__device__ __forceinline__ void unpack2(u64 v, float& lo, float& hi) {
    asm("mov.b64 {%0, %1}, %2;" : "=f"(lo), "=f"(hi) : "l"(v));
}
__device__ __forceinline__ u64 ex2_pair(u64 t) {
    u64 e;
    asm("{\n\t"
        ".reg .f32 e0, e1;\n\t"
        "mov.b64 {e0, e1}, %1;\n\t"
        "ex2.approx.ftz.f32 e0, e0;\n\t"
        "ex2.approx.ftz.f32 e1, e1;\n\t"
        "mov.b64 %0, {e0, e1};\n\t"
        "}" : "=l"(e) : "l"(t));
    return e;
}

// Packed-lane = 2 adjacent CENTERS. Per pair p: 56 B
//   sA[p] = {c0x,c1x, c0y,c1y}
//   sB[p] = {c0z,c1z, cs0,cs1}    cs = -K*|c|^2
//   sQ[p] = {u0,u1,  v0,v1}
//   sW[p] = {w0,w1}
__global__ __launch_bounds__(BLOCK, 2)
void rbf_kernel(const float* __restrict__ x, const float* __restrict__ cen,
                const float* __restrict__ cu, const float* __restrict__ cv,
                const float* __restrict__ cw,
                int n, int m, int Ph, int gridP, int tot)
{
    extern __shared__ float4 sm[];
    float4* sA = sm;
    float4* sB = sm + Ph;
    float4* sQ = sm + 2 * Ph;
    float2* sW = (float2*)(sm + 3 * Ph);

    int pb   = blockIdx.x % gridP;   // point-block
    int half = blockIdx.x / gridP;   // which center half
    int pbase = half * Ph;           // first center-pair of this half

    for (int p = threadIdx.x; p < Ph; p += BLOCK) {
        int gp = pbase + p;
        float c[2][3], cs[2], qu[2], qv[2], qw[2];
#pragma unroll
        for (int h = 0; h < 2; h++) {
            int e = 2 * gp + h;
            if (e < m) {
                c[h][0] = cen[3*e]; c[h][1] = cen[3*e+1]; c[h][2] = cen[3*e+2];
                cs[h] = -KCONST * (c[h][0]*c[h][0] + c[h][1]*c[h][1] + c[h][2]*c[h][2]);
                qu[h] = cu[e]; qv[h] = cv[e]; qw[h] = cw[e];
            } else {
                // pad: exponent -> -1e30 => ex2 -> 0; coeffs 0 => no contribution
                c[h][0] = c[h][1] = c[h][2] = 0.f;
                cs[h] = -1e30f;
                qu[h] = qv[h] = qw[h] = 0.f;
            }
        }
        sA[p] = make_float4(c[0][0], c[1][0], c[0][1], c[1][1]);
        sB[p] = make_float4(c[0][2], c[1][2], cs[0], cs[1]);
        sQ[p] = make_float4(qu[0], qu[1], qv[0], qv[1]);
        sW[p] = make_float2(qw[0], qw[1]);
    }
    __syncthreads();

    int g = pb * BLOCK + threadIdx.x;

    u64 a0p[PTS], a1p[PTS], a2p[PTS], bbp[PTS];
#pragma unroll
    for (int s = 0; s < PTS; s++) {
        int i = g + s * tot;
        int ic = (i < n) ? i : 0;     // clamp loads; stores guarded below
        float x0 = x[3*ic], x1 = x[3*ic+1], x2 = x[3*ic+2];
        float a0 = 2.f * KCONST * x0;
        float a1 = 2.f * KCONST * x1;
        float a2 = 2.f * KCONST * x2;
        float bb = -KCONST * (x0*x0 + x1*x1 + x2*x2);
        a0p[s] = pack2(a0, a0);
        a1p[s] = pack2(a1, a1);
        a2p[s] = pack2(a2, a2);
        bbp[s] = pack2(bb, bb);
    }

    u64 su[PTS], sv[PTS], sw[PTS];   // packed over the 2 center lanes
#pragma unroll
    for (int s = 0; s < PTS; s++) { su[s] = 0; sv[s] = 0; sw[s] = 0; }

    const ulonglong2* pA = (const ulonglong2*)sA;
    const ulonglong2* pB = (const ulonglong2*)sB;
    const ulonglong2* pQ = (const ulonglong2*)sQ;
    const u64*        pW = (const u64*)sW;

#pragma unroll 2
    for (int p = 0; p < Ph; p++) {
        ulonglong2 cxy = pA[p];   // .x = {c0x,c1x}, .y = {c0y,c1y}
        ulonglong2 czs = pB[p];   // .x = {c0z,c1z}, .y = {cs0,cs1}
        ulonglong2 quv = pQ[p];   // .x = {u0,u1},   .y = {v0,v1}
        u64        qw  = pW[p];   // {w0,w1}

#pragma unroll
        for (int s = 0; s < PTS; s++) {
            // t = 2K*x.c - K|x|^2 - K|c|^2  (packed over 2 centers)
            u64 t = add2(czs.y, bbp[s]);
            t = fma2(a2p[s], czs.x, t);
            t = fma2(a1p[s], cxy.y, t);
            t = fma2(a0p[s], cxy.x, t);

            u64 e = ex2_pair(t);

            su[s] = fma2(e, quv.x, su[s]);
            sv[s] = fma2(e, quv.y, sv[s]);
            sw[s] = fma2(e, qw,    sw[s]);
        }
    }

    float* part = g_partial + (size_t)half * NPMAX * 3;
#pragma unroll
    for (int s = 0; s < PTS; s++) {
        int i = g + s * tot;
        if (i < n) {
            float u0, u1, v0, v1, w0, w1;
            unpack2(su[s], u0, u1);
            unpack2(sv[s], v0, v1);
            unpack2(sw[s], w0, w1);
            part[3*i]   = u0 + u1;
            part[3*i+1] = v0 + v1;
            part[3*i+2] = w0 + w1;
        }
    }
}

__global__ void combine_kernel(const float* __restrict__ x,
                               float* __restrict__ out, int n)
{
    int i = blockIdx.x * blockDim.x + threadIdx.x;
    if (i >= n) return;
    float x0 = x[3*i], x1 = x[3*i+1], x2 = x[3*i+2];
    float r  = sqrtf(x0*x0 + x1*x1 + x2*x2);
    float om = 1.f - r;                       // base = x * (1 - ||x||)
    const float* p0 = g_partial;
    const float* p1 = g_partial + (size_t)NPMAX * 3;
    out[3*i]   = fmaf(x0, om, p0[3*i]   + p1[3*i]);
    out[3*i+1] = fmaf(x1, om, p0[3*i+1] + p1[3*i+1]);
    out[3*i+2] = fmaf(x2, om, p0[3*i+2] + p1[3*i+2]);
}

extern "C" void kernel_launch(void* const* d_in, const int* in_sizes, int n_in,
                              void* d_out, int out_size)
{
    const float* x   = (const float*)d_in[0];
    const float* cen = (const float*)d_in[1];
    const float* cu  = (const float*)d_in[2];
    const float* cv  = (const float*)d_in[3];
    const float* cw  = (const float*)d_in[4];
    float* out = (float*)d_out;

    int n = in_sizes[0] / 3;     // 100000
    int m = in_sizes[2];         // 3375
    int P  = (m + 1) / 2;        // 1688 center pairs (pad to even)
    int Ph = (P + 1) / 2;        // 844 pairs per half

    // 3 * float4 + 1 * float2 per pair = 56 B -> 47.25 KB per CTA (2 CTAs/SM)
    size_t smem = (size_t)Ph * (3 * sizeof(float4) + sizeof(float2));
    cudaFuncSetAttribute(rbf_kernel,
                         cudaFuncAttributeMaxDynamicSharedMemorySize,
                         (int)smem);

    int gridP = (n + BLOCK * PTS - 1) / (BLOCK * PTS);   // 131 point-blocks
    int tot   = gridP * BLOCK;
    rbf_kernel<<<2 * gridP, BLOCK, smem>>>(x, cen, cu, cv, cw,
                                           n, m, Ph, gridP, tot);
    combine_kernel<<<(n + 255) / 256, 256>>>(x, out, n);
}